// round 16
// baseline (speedup 1.0000x reference)
#include <cuda_runtime.h>
#include <cuda_fp16.h>
#include <cstdint>

// ---------------- problem constants ----------------
#define L_LEVELS 16
#define T_SIZE 32768
#define TMASK  32767u
#define P1 2654435761u
#define P2 805459861u
#define MAXN (1 << 20)
#define NBINS 32768
#define BLOCK2 128
#define CONV_BLOCKS 4096   // 4096*256 = 1,048,576 half2 pairs

typedef unsigned long long u64;

// scratch (no cudaMalloc allowed)
__device__ float4 g_tmp[MAXN];
__device__ float4 g_pts[MAXN];
__device__ unsigned g_keys[MAXN];
__device__ int g_hist[NBINS];
__device__ int g_off[NBINS];      // within-segment exclusive offsets
__device__ int g_blocksum[64];    // per-segment totals
__device__ int g_count;
__device__ __half g_tblh[L_LEVELS * T_SIZE * 4];   // 4 MB fp16 table

__device__ __forceinline__ unsigned part5(unsigned x) {
    return ((x & 16u) << 8) | ((x & 8u) << 6) | ((x & 4u) << 4) |
           ((x & 2u) << 2) | (x & 1u);
}

// ---------------- packed f32x2 helpers ----------------
__device__ __forceinline__ u64 pk2(float x, float y) {
    u64 r; asm("mov.b64 %0,{%1,%2};" : "=l"(r) : "f"(x), "f"(y)); return r;
}
__device__ __forceinline__ float2 up2(u64 v) {
    float2 f; asm("mov.b64 {%0,%1},%2;" : "=f"(f.x), "=f"(f.y) : "l"(v)); return f;
}
__device__ __forceinline__ void ffma2(u64& d, u64 a, u64 b) {
    asm("fma.rn.f32x2 %0,%1,%2,%0;" : "+l"(d) : "l"(a), "l"(b));
}

// ---------------- kernel 1: convert + mask + compact + histogram --------
__global__ void k_convert_mask(const float* __restrict__ t,
                               const float* __restrict__ xyz,
                               const float* __restrict__ bmin,
                               const float* __restrict__ bmax,
                               float* __restrict__ out, int N)
{
    if ((int)blockIdx.x < CONV_BLOCKS) {
        int i = blockIdx.x * 256 + threadIdx.x;
        float2 v = ((const float2*)t)[i];
        ((__half2*)g_tblh)[i] = __floats2half2_rn(v.x, v.y);
        return;
    }

    int i = (blockIdx.x - CONV_BLOCKS) * 256 + threadIdx.x;
    bool inb = false;
    float cx = 0.f, cy = 0.f, cz = 0.f;

    if (i < N) {
        float bx0 = bmin[0], by0 = bmin[1], bz0 = bmin[2];
        float bx1 = bmax[0], by1 = bmax[1], bz1 = bmax[2];
        float x = xyz[3 * i + 0];
        float y = xyz[3 * i + 1];
        float z = xyz[3 * i + 2];
        cx = (x - bx0) / (bx1 - bx0);
        cy = (y - by0) / (by1 - by0);
        cz = (z - bz0) / (bz1 - bz0);
        inb = (cx >= 0.f) & (cx <= 1.f) &
              (cy >= 0.f) & (cy <= 1.f) &
              (cz >= 0.f) & (cz <= 1.f);

        out[i] = inb ? 1.f : 0.f;
        float* dxyz = out + N;
        float* drot = out + (size_t)4 * N;
        dxyz[3 * i + 0] = 0.f;
        dxyz[3 * i + 1] = 0.f;
        dxyz[3 * i + 2] = 0.f;
        drot[4 * i + 0] = 1.f;
        drot[4 * i + 1] = 0.f;
        drot[4 * i + 2] = 0.f;
        drot[4 * i + 3] = 0.f;
    }

    unsigned m = __ballot_sync(0xffffffffu, inb);
    if (inb) {
        int lane = threadIdx.x & 31;
        int leader = __ffs(m) - 1;
        int base = 0;
        if (lane == leader) base = atomicAdd(&g_count, __popc(m));
        base = __shfl_sync(m, base, leader);
        int slot = base + __popc(m & ((1u << lane) - 1u));
        cx = fminf(fmaxf(cx, 0.f), 1.f);
        cy = fminf(fmaxf(cy, 0.f), 1.f);
        cz = fminf(fmaxf(cz, 0.f), 1.f);
        g_tmp[slot] = make_float4(cx, cy, cz, __int_as_float(i));
        unsigned qx = min(31u, (unsigned)(cx * 32.f));
        unsigned qy = min(31u, (unsigned)(cy * 32.f));
        unsigned qz = min(31u, (unsigned)(cz * 32.f));
        unsigned key = part5(qx) | (part5(qy) << 1) | (part5(qz) << 2);
        g_keys[slot] = key;
        atomicAdd(&g_hist[key], 1);
    }
}

// ---------------- kernel 2: scanA — 64 blocks, local scan of 512 bins ---
__global__ void k_scanA()
{
    __shared__ int wsum[16];
    int b = blockIdx.x;
    int tid = threadIdx.x;            // 128 threads, 4 bins each
    int base = b * 512 + tid * 4;
    int4 c = *(const int4*)&g_hist[base];
    int s = c.x + c.y + c.z + c.w;

    int lane = tid & 31, wid = tid >> 5;
    int v = s;
    #pragma unroll
    for (int d = 1; d < 32; d <<= 1) {
        int t = __shfl_up_sync(0xffffffffu, v, d);
        if (lane >= d) v += t;
    }
    if (lane == 31) wsum[wid] = v;
    __syncthreads();
    if (tid == 0) {
        int acc = 0;
        #pragma unroll
        for (int w = 0; w < 4; w++) { int t = wsum[w]; wsum[w] = acc; acc += t; }
        g_blocksum[b] = acc;
    }
    __syncthreads();
    int excl = v - s + wsum[wid];
    int4 o;
    o.x = excl; o.y = excl + c.x; o.z = o.y + c.y; o.w = o.z + c.z;
    *(int4*)&g_off[base] = o;
}

// ---------------- kernel 3: scatter (with on-the-fly segment prefix) ----
__global__ void k_scatter()
{
    __shared__ int pre[64];
    __shared__ int w0tot;
    int tid = threadIdx.x;            // 256 threads
    if (tid < 64) {
        int lane = tid & 31;
        int s = g_blocksum[tid];
        int v = s;
        #pragma unroll
        for (int d = 1; d < 32; d <<= 1) {
            int t = __shfl_up_sync(0xffffffffu, v, d);
            if (lane >= d) v += t;
        }
        if (tid == 31) w0tot = v;
        pre[tid] = v - s;
    }
    __syncthreads();
    if (tid < 64 && tid >= 32) pre[tid] += w0tot;
    __syncthreads();

    int cnt = g_count;
    for (int i = blockIdx.x * blockDim.x + tid; i < cnt;
         i += gridDim.x * blockDim.x) {
        float4 p = g_tmp[i];
        unsigned key = g_keys[i];
        int pos = atomicAdd(&g_off[key], 1) + pre[key >> 9];
        g_pts[pos] = p;
    }
}

// ---------------- encode helpers ----------------
__device__ __forceinline__ void issue_level(
    const uint2* __restrict__ tbl, float cx, float cy, float cz,
    float sc, unsigned lvl, uint2* raw, float& tx, float& ty, float& tz)
{
    float px = cx * sc, py = cy * sc, pz = cz * sc;
    float fx = floorf(px), fy = floorf(py), fz = floorf(pz);
    tx = px - fx; ty = py - fy; tz = pz - fz;
    unsigned ux = (unsigned)fx, uy = (unsigned)fy, uz = (unsigned)fz;
    unsigned hx0 = ux,      hx1 = ux + 1u;
    unsigned hy0 = uy * P1, hy1 = hy0 + P1;
    unsigned hz0 = uz * P2, hz1 = hz0 + P2;
    unsigned base = lvl * T_SIZE;
    #pragma unroll
    for (int c = 0; c < 8; c++) {
        unsigned hx = (c & 4) ? hx1 : hx0;
        unsigned hy = (c & 2) ? hy1 : hy0;
        unsigned hz = (c & 1) ? hz1 : hz0;
        raw[c] = __ldg(tbl + (base + ((hx ^ hy ^ hz) & TMASK)));
    }
}

__device__ __forceinline__ void consume_level(
    const uint2* raw, float tx, float ty, float tz,
    float& a0, float& a1, float& a2, float& a3)
{
    float wxv[2] = {1.f - tx, tx};
    float wyv[2] = {1.f - ty, ty};
    float wzv[2] = {1.f - tz, tz};
    a0 = 0.f; a1 = 0.f; a2 = 0.f; a3 = 0.f;
    #pragma unroll
    for (int c = 0; c < 8; c++) {
        __half2 q01 = *reinterpret_cast<const __half2*>(&raw[c].x);
        __half2 q23 = *reinterpret_cast<const __half2*>(&raw[c].y);
        float2 f01 = __half22float2(q01);
        float2 f23 = __half22float2(q23);
        float w = wxv[(c >> 2) & 1] * wyv[(c >> 1) & 1] * wzv[c & 1];
        a0 += w * f01.x; a1 += w * f01.y;
        a2 += w * f23.x; a3 += w * f23.y;
    }
}

// ---------------- kernel 4: phase-decoupled encode + MLP, 4 blocks/SM ---
// smem: [w0 16KB][w1 16KB][w2 2KB][acts fp16 16KB] = 50KB
#define SW0_OFF  0                       // bytes
#define SW1_OFF  16384
#define SW2_OFF  32768
#define SACT_OFF 34816                   // 32 half2-rows x BLOCK2
#define SMEM_BYTES (34816 + 32 * BLOCK2 * 4)   // 51200

__global__ __launch_bounds__(BLOCK2, 4)
void k_encode_mlp(const float* __restrict__ w0,
                  const float* __restrict__ w1,
                  const float* __restrict__ w2,
                  float* __restrict__ out, int N)
{
    extern __shared__ char smc[];
    float*   sw0   = (float*)(smc + SW0_OFF);    // 4096 floats
    float*   sw1   = (float*)(smc + SW1_OFF);    // 4096 floats
    float*   sw2   = (float*)(smc + SW2_OFF);    // 512 floats
    __half2* sact2 = (__half2*)(smc + SACT_OFF); // 32 rows x BLOCK2

    int tid = threadIdx.x;
    int cnt = g_count;
    if ((int)(blockIdx.x * BLOCK2) >= cnt) return;

    for (int k = tid; k < 4096 / 4; k += BLOCK2)
        ((float4*)sw0)[k] = ((const float4*)w0)[k];
    for (int k = tid; k < 4096 / 4; k += BLOCK2)
        ((float4*)sw1)[k] = ((const float4*)w1)[k];
    for (int k = tid; k < 512 / 4; k += BLOCK2)
        ((float4*)sw2)[k] = ((const float4*)w2)[k];
    __syncthreads();

    const uint2* tbl = (const uint2*)g_tblh;
    const ulonglong2* w0v = (const ulonglong2*)sw0;  // row = 16 units
    const ulonglong2* w1v = (const ulonglong2*)sw1;
    float* dxyz = out + N;
    float* drot = out + (size_t)4 * N;

    for (int slot = blockIdx.x * BLOCK2 + tid; slot < cnt;
         slot += gridDim.x * BLOCK2) {
        float4 p = g_pts[slot];
        float cx = p.x, cy = p.y, cz = p.z;
        int ipt = __float_as_int(p.w);

        // ================= PHASE 1: encode (depth-2 gather pipeline) ====
        {
            uint2 rawA[8], rawB[8];
            float txA, tyA, tzA, txB, tyB, tzB;
            issue_level(tbl, cx, cy, cz, 16.f, 0, rawA, txA, tyA, tzA);
            issue_level(tbl, cx, cy, cz, 32.f, 1, rawB, txB, tyB, tzB);
            float scA = 64.f, scB = 128.f;   // scales of next A/B issues

            #pragma unroll 1
            for (int lp = 0; lp < 8; lp++) {
                int l0 = 2 * lp;
                float a0, a1, a2, a3;
                consume_level(rawA, txA, tyA, tzA, a0, a1, a2, a3);
                if (lp < 7)
                    issue_level(tbl, cx, cy, cz, scA, (unsigned)(l0 + 2),
                                rawA, txA, tyA, tzA);
                sact2[(l0 * 2 + 0) * BLOCK2 + tid] = __floats2half2_rn(a0, a1);
                sact2[(l0 * 2 + 1) * BLOCK2 + tid] = __floats2half2_rn(a2, a3);

                consume_level(rawB, txB, tyB, tzB, a0, a1, a2, a3);
                if (lp < 7)
                    issue_level(tbl, cx, cy, cz, scB, (unsigned)(l0 + 3),
                                rawB, txB, tyB, tzB);
                sact2[(l0 * 2 + 2) * BLOCK2 + tid] = __floats2half2_rn(a0, a1);
                sact2[(l0 * 2 + 3) * BLOCK2 + tid] = __floats2half2_rn(a2, a3);

                scA *= 4.f; scB *= 4.f;
            }
        }

        // ================= PHASE 2: MLP ==================================
        u64 h2[32];
        #pragma unroll
        for (int j = 0; j < 32; j++) h2[j] = 0ull;

        // layer 1: acts = enc (fp16 pairs), weights fp32, FFMA2
        #pragma unroll 2
        for (int i2 = 0; i2 < 32; i2++) {
            __half2 hh = sact2[i2 * BLOCK2 + tid];
            float2 vf = __half22float2(hh);
            u64 v0 = pk2(vf.x, vf.x);
            u64 v1 = pk2(vf.y, vf.y);
            const ulonglong2* r0 = w0v + (i2 << 5);   // row 2*i2
            const ulonglong2* r1 = r0 + 16;           // row 2*i2+1
            #pragma unroll
            for (int j = 0; j < 16; j++) {
                ulonglong2 wa = r0[j];
                ffma2(h2[2 * j + 0], v0, wa.x);
                ffma2(h2[2 * j + 1], v0, wa.y);
            }
            #pragma unroll
            for (int j = 0; j < 16; j++) {
                ulonglong2 wb = r1[j];
                ffma2(h2[2 * j + 0], v1, wb.x);
                ffma2(h2[2 * j + 1], v1, wb.y);
            }
        }

        // relu -> overwrite act region (enc fully consumed)
        #pragma unroll
        for (int j = 0; j < 32; j++) {
            float2 t = up2(h2[j]);
            sact2[j * BLOCK2 + tid] =
                __floats2half2_rn(fmaxf(t.x, 0.f), fmaxf(t.y, 0.f));
            h2[j] = 0ull;
        }

        // layer 2: same structure; h1 stays in registers
        #pragma unroll 2
        for (int i2 = 0; i2 < 32; i2++) {
            __half2 hh = sact2[i2 * BLOCK2 + tid];
            float2 vf = __half22float2(hh);
            u64 v0 = pk2(vf.x, vf.x);
            u64 v1 = pk2(vf.y, vf.y);
            const ulonglong2* r0 = w1v + (i2 << 5);
            const ulonglong2* r1 = r0 + 16;
            #pragma unroll
            for (int j = 0; j < 16; j++) {
                ulonglong2 wa = r0[j];
                ffma2(h2[2 * j + 0], v0, wa.x);
                ffma2(h2[2 * j + 1], v0, wa.y);
            }
            #pragma unroll
            for (int j = 0; j < 16; j++) {
                ulonglong2 wb = r1[j];
                ffma2(h2[2 * j + 0], v1, wb.x);
                ffma2(h2[2 * j + 1], v1, wb.y);
            }
        }

        // layer 3: h1 from registers, w2 fp32
        float o[8];
        #pragma unroll
        for (int k = 0; k < 8; k++) o[k] = 0.f;
        #pragma unroll 8
        for (int j = 0; j < 32; j++) {
            float2 t = up2(h2[j]);
            float va = fmaxf(t.x, 0.f);
            float vb = fmaxf(t.y, 0.f);
            const float4* wr = (const float4*)(sw2 + ((2 * j) << 3));
            float4 wa = wr[0], wb4 = wr[1];   // row 2j
            float4 wc = wr[2], wd = wr[3];    // row 2j+1
            o[0] += va * wa.x + vb * wc.x;
            o[1] += va * wa.y + vb * wc.y;
            o[2] += va * wa.z + vb * wc.z;
            o[3] += va * wa.w + vb * wc.w;
            o[4] += va * wb4.x + vb * wd.x;
            o[5] += va * wb4.y + vb * wd.y;
            o[6] += va * wb4.z + vb * wd.z;
            o[7] += va * wb4.w + vb * wd.w;
        }

        dxyz[3 * ipt + 0] = o[0];
        dxyz[3 * ipt + 1] = o[1];
        dxyz[3 * ipt + 2] = o[2];
        drot[4 * ipt + 0] = o[3];
        drot[4 * ipt + 1] = o[4];
        drot[4 * ipt + 2] = o[5];
        drot[4 * ipt + 3] = o[6];
    }
}

// ---------------- launch ----------------
extern "C" void kernel_launch(void* const* d_in, const int* in_sizes, int n_in,
                              void* d_out, int out_size)
{
    const float* xyz   = (const float*)d_in[0];
    const float* bmin  = (const float*)d_in[1];
    const float* bmax  = (const float*)d_in[2];
    const float* table = (const float*)d_in[3];
    const float* w0    = (const float*)d_in[4];
    const float* w1    = (const float*)d_in[5];
    const float* w2    = (const float*)d_in[6];
    int N = in_sizes[0] / 3;
    float* out = (float*)d_out;

    void* ptr = nullptr;
    cudaGetSymbolAddress(&ptr, g_count);
    cudaMemsetAsync(ptr, 0, sizeof(int), 0);
    cudaGetSymbolAddress(&ptr, g_hist);
    cudaMemsetAsync(ptr, 0, NBINS * sizeof(int), 0);

    int grid1 = CONV_BLOCKS + (N + 255) / 256;
    k_convert_mask<<<grid1, 256>>>(table, xyz, bmin, bmax, out, N);   // #1
    k_scanA<<<64, 128>>>();                                           // #2
    k_scatter<<<512, 256>>>();                                        // #3
    cudaFuncSetAttribute(k_encode_mlp,
                         cudaFuncAttributeMaxDynamicSharedMemorySize, SMEM_BYTES);
    k_encode_mlp<<<592, BLOCK2, SMEM_BYTES>>>(w0, w1, w2, out, N);    // #4
}

// round 17
// speedup vs baseline: 1.0929x; 1.0929x over previous
#include <cuda_runtime.h>
#include <cuda_fp16.h>
#include <cstdint>

// ---------------- problem constants ----------------
#define L_LEVELS 16
#define T_SIZE 32768
#define TMASK  32767u
#define P1 2654435761u
#define P2 805459861u
#define MAXN (1 << 20)
#define NBINS 32768
#define BLOCK2 128
#define CONV_BLOCKS 4096   // 4096*256 = 1,048,576 half2 pairs

typedef unsigned long long u64;

// scratch (no cudaMalloc allowed)
__device__ float4 g_tmp[MAXN];
__device__ float4 g_pts[MAXN];
__device__ unsigned g_keys[MAXN];
__device__ int g_hist[NBINS];
__device__ int g_off[NBINS];      // within-segment exclusive offsets
__device__ int g_blocksum[64];    // per-segment totals
__device__ int g_count;
__device__ int g_tile;            // dynamic tile counter
__device__ __half g_tblh[L_LEVELS * T_SIZE * 4];   // 4 MB fp16 table

__device__ __forceinline__ unsigned part5(unsigned x) {
    return ((x & 16u) << 8) | ((x & 8u) << 6) | ((x & 4u) << 4) |
           ((x & 2u) << 2) | (x & 1u);
}

// ---------------- packed f32x2 helpers ----------------
__device__ __forceinline__ u64 pk2(float x, float y) {
    u64 r; asm("mov.b64 %0,{%1,%2};" : "=l"(r) : "f"(x), "f"(y)); return r;
}
__device__ __forceinline__ float2 up2(u64 v) {
    float2 f; asm("mov.b64 {%0,%1},%2;" : "=f"(f.x), "=f"(f.y) : "l"(v)); return f;
}
__device__ __forceinline__ void ffma2(u64& d, u64 a, u64 b) {
    asm("fma.rn.f32x2 %0,%1,%2,%0;" : "+l"(d) : "l"(a), "l"(b));
}

// ---------------- kernel 1: convert + mask + compact + histogram --------
__global__ void k_convert_mask(const float* __restrict__ t,
                               const float* __restrict__ xyz,
                               const float* __restrict__ bmin,
                               const float* __restrict__ bmax,
                               float* __restrict__ out, int N)
{
    if ((int)blockIdx.x < CONV_BLOCKS) {
        int i = blockIdx.x * 256 + threadIdx.x;
        float2 v = ((const float2*)t)[i];
        ((__half2*)g_tblh)[i] = __floats2half2_rn(v.x, v.y);
        return;
    }

    int i = (blockIdx.x - CONV_BLOCKS) * 256 + threadIdx.x;
    bool inb = false;
    float cx = 0.f, cy = 0.f, cz = 0.f;

    if (i < N) {
        float bx0 = bmin[0], by0 = bmin[1], bz0 = bmin[2];
        float bx1 = bmax[0], by1 = bmax[1], bz1 = bmax[2];
        float x = xyz[3 * i + 0];
        float y = xyz[3 * i + 1];
        float z = xyz[3 * i + 2];
        cx = (x - bx0) / (bx1 - bx0);
        cy = (y - by0) / (by1 - by0);
        cz = (z - bz0) / (bz1 - bz0);
        inb = (cx >= 0.f) & (cx <= 1.f) &
              (cy >= 0.f) & (cy <= 1.f) &
              (cz >= 0.f) & (cz <= 1.f);

        out[i] = inb ? 1.f : 0.f;
        float* dxyz = out + N;
        float* drot = out + (size_t)4 * N;
        dxyz[3 * i + 0] = 0.f;
        dxyz[3 * i + 1] = 0.f;
        dxyz[3 * i + 2] = 0.f;
        drot[4 * i + 0] = 1.f;
        drot[4 * i + 1] = 0.f;
        drot[4 * i + 2] = 0.f;
        drot[4 * i + 3] = 0.f;
    }

    unsigned m = __ballot_sync(0xffffffffu, inb);
    if (inb) {
        int lane = threadIdx.x & 31;
        int leader = __ffs(m) - 1;
        int base = 0;
        if (lane == leader) base = atomicAdd(&g_count, __popc(m));
        base = __shfl_sync(m, base, leader);
        int slot = base + __popc(m & ((1u << lane) - 1u));
        cx = fminf(fmaxf(cx, 0.f), 1.f);
        cy = fminf(fmaxf(cy, 0.f), 1.f);
        cz = fminf(fmaxf(cz, 0.f), 1.f);
        g_tmp[slot] = make_float4(cx, cy, cz, __int_as_float(i));
        unsigned qx = min(31u, (unsigned)(cx * 32.f));
        unsigned qy = min(31u, (unsigned)(cy * 32.f));
        unsigned qz = min(31u, (unsigned)(cz * 32.f));
        unsigned key = part5(qx) | (part5(qy) << 1) | (part5(qz) << 2);
        g_keys[slot] = key;
        atomicAdd(&g_hist[key], 1);
    }
}

// ---------------- kernel 2: scanA — 64 blocks, local scan of 512 bins ---
__global__ void k_scanA()
{
    __shared__ int wsum[16];
    int b = blockIdx.x;
    int tid = threadIdx.x;            // 128 threads, 4 bins each
    int base = b * 512 + tid * 4;
    int4 c = *(const int4*)&g_hist[base];
    int s = c.x + c.y + c.z + c.w;

    int lane = tid & 31, wid = tid >> 5;
    int v = s;
    #pragma unroll
    for (int d = 1; d < 32; d <<= 1) {
        int t = __shfl_up_sync(0xffffffffu, v, d);
        if (lane >= d) v += t;
    }
    if (lane == 31) wsum[wid] = v;
    __syncthreads();
    if (tid == 0) {
        int acc = 0;
        #pragma unroll
        for (int w = 0; w < 4; w++) { int t = wsum[w]; wsum[w] = acc; acc += t; }
        g_blocksum[b] = acc;
    }
    __syncthreads();
    int excl = v - s + wsum[wid];
    int4 o;
    o.x = excl; o.y = excl + c.x; o.z = o.y + c.y; o.w = o.z + c.z;
    *(int4*)&g_off[base] = o;
}

// ---------------- kernel 3: scatter (with on-the-fly segment prefix) ----
__global__ void k_scatter()
{
    __shared__ int pre[64];
    __shared__ int w0tot;
    int tid = threadIdx.x;            // 256 threads
    if (tid < 64) {
        int lane = tid & 31;
        int s = g_blocksum[tid];
        int v = s;
        #pragma unroll
        for (int d = 1; d < 32; d <<= 1) {
            int t = __shfl_up_sync(0xffffffffu, v, d);
            if (lane >= d) v += t;
        }
        if (tid == 31) w0tot = v;
        pre[tid] = v - s;
    }
    __syncthreads();
    if (tid < 64 && tid >= 32) pre[tid] += w0tot;
    __syncthreads();

    int cnt = g_count;
    for (int i = blockIdx.x * blockDim.x + tid; i < cnt;
         i += gridDim.x * blockDim.x) {
        float4 p = g_tmp[i];
        unsigned key = g_keys[i];
        int pos = atomicAdd(&g_off[key], 1) + pre[key >> 9];
        g_pts[pos] = p;
    }
}

// ---------------- kernel 4: pipelined encode + FFMA2 MLP ----------------
// smem: [w0 16KB][w1 16KB][w2 2KB][act 64*BLOCK2*4 = 32KB] = 66KB
#define SW0_OFF  0                       // bytes
#define SW1_OFF  16384
#define SW2_OFF  32768
#define SACT_OFF 34816
#define SMEM_BYTES (34816 + 64 * BLOCK2 * 4)

__global__ __launch_bounds__(BLOCK2, 3)
void k_encode_mlp(const float* __restrict__ w0,
                  const float* __restrict__ w1,
                  const float* __restrict__ w2,
                  float* __restrict__ out, int N)
{
    extern __shared__ char smc[];
    float* sw0  = (float*)(smc + SW0_OFF);    // 4096 floats
    float* sw1  = (float*)(smc + SW1_OFF);    // 4096 floats
    float* sw2  = (float*)(smc + SW2_OFF);    // 512 floats
    float* sact = (float*)(smc + SACT_OFF);   // 64 * BLOCK2

    __shared__ int s_tile;
    int tid = threadIdx.x;
    int cnt = g_count;
    int ntiles = (cnt + BLOCK2 - 1) / BLOCK2;
    if ((int)blockIdx.x >= ntiles) return;

    for (int k = tid; k < 4096 / 4; k += BLOCK2)
        ((float4*)sw0)[k] = ((const float4*)w0)[k];
    for (int k = tid; k < 4096 / 4; k += BLOCK2)
        ((float4*)sw1)[k] = ((const float4*)w1)[k];
    for (int k = tid; k < 512 / 4; k += BLOCK2)
        ((float4*)sw2)[k] = ((const float4*)w2)[k];
    __syncthreads();

    const uint2* tbl = (const uint2*)g_tblh;
    const ulonglong2* w0v = (const ulonglong2*)sw0;  // 16B = 2 f32x2 pairs
    const ulonglong2* w1v = (const ulonglong2*)sw1;
    float* dxyz = out + N;
    float* drot = out + (size_t)4 * N;

    for (;;) {
        // ---- dynamic tile claim ----
        if (tid == 0) s_tile = atomicAdd(&g_tile, 1);
        __syncthreads();
        int tile = s_tile;
        __syncthreads();            // protect s_tile before next claim
        if (tile >= ntiles) break;

        int slot = tile * BLOCK2 + tid;
        bool active = slot < cnt;
        float4 p = active ? g_pts[slot] : make_float4(0.f, 0.f, 0.f, 0.f);
        float cx = p.x, cy = p.y, cz = p.z;
        int ipt = __float_as_int(p.w);

        // packed layer accumulator: h2[k] holds outputs (2k, 2k+1)
        u64 h2[32];
        #pragma unroll
        for (int j = 0; j < 32; j++) h2[j] = 0ull;

        // pipelined encode: raw[8] pending + pending corner weights
        uint2 raw[8];
        float cw[8];

        {   // prologue: level 0 loads
            float px = cx * 16.f, py = cy * 16.f, pz = cz * 16.f;
            float fx = floorf(px), fy = floorf(py), fz = floorf(pz);
            float tx = px - fx, ty = py - fy, tz = pz - fz;
            unsigned ux = (unsigned)fx, uy = (unsigned)fy, uz = (unsigned)fz;
            unsigned hx0 = ux,      hx1 = ux + 1u;
            unsigned hy0 = uy * P1, hy1 = hy0 + P1;
            unsigned hz0 = uz * P2, hz1 = hz0 + P2;
            float wxv[2] = {1.f - tx, tx};
            float wyv[2] = {1.f - ty, ty};
            float wzv[2] = {1.f - tz, tz};
            #pragma unroll
            for (int c = 0; c < 8; c++) {
                unsigned hx = (c & 4) ? hx1 : hx0;
                unsigned hy = (c & 2) ? hy1 : hy0;
                unsigned hz = (c & 1) ? hz1 : hz0;
                raw[c] = __ldg(tbl + ((hx ^ hy ^ hz) & TMASK));
                cw[c] = wxv[(c >> 2) & 1] * wyv[(c >> 1) & 1] * wzv[c & 1];
            }
        }

        float sc = 32.f;
        #pragma unroll 1
        for (int l = 0; l < L_LEVELS; l++) {
            // 1) consume pending gathers
            float a0 = 0.f, a1 = 0.f, a2 = 0.f, a3 = 0.f;
            #pragma unroll
            for (int c = 0; c < 8; c++) {
                __half2 q01 = *reinterpret_cast<__half2*>(&raw[c].x);
                __half2 q23 = *reinterpret_cast<__half2*>(&raw[c].y);
                float2 f01 = __half22float2(q01);
                float2 f23 = __half22float2(q23);
                float w = cw[c];
                a0 += w * f01.x; a1 += w * f01.y;
                a2 += w * f23.x; a3 += w * f23.y;
            }

            // 2) issue next level's gathers
            if (l + 1 < L_LEVELS) {
                float px = cx * sc, py = cy * sc, pz = cz * sc;
                float fx = floorf(px), fy = floorf(py), fz = floorf(pz);
                float tx = px - fx, ty = py - fy, tz = pz - fz;
                unsigned ux = (unsigned)fx, uy = (unsigned)fy, uz = (unsigned)fz;
                unsigned hx0 = ux,      hx1 = ux + 1u;
                unsigned hy0 = uy * P1, hy1 = hy0 + P1;
                unsigned hz0 = uz * P2, hz1 = hz0 + P2;
                unsigned base = (unsigned)(l + 1) * T_SIZE;
                float wxv[2] = {1.f - tx, tx};
                float wyv[2] = {1.f - ty, ty};
                float wzv[2] = {1.f - tz, tz};
                #pragma unroll
                for (int c = 0; c < 8; c++) {
                    unsigned hx = (c & 4) ? hx1 : hx0;
                    unsigned hy = (c & 2) ? hy1 : hy0;
                    unsigned hz = (c & 1) ? hz1 : hz0;
                    raw[c] = __ldg(tbl + (base + ((hx ^ hy ^ hz) & TMASK)));
                    cw[c] = wxv[(c >> 2) & 1] * wyv[(c >> 1) & 1] * wzv[c & 1];
                }
                sc *= 2.f;
            }

            // 3) layer-1 FFMA2 block: 4 features x 32 packed FMAs
            float av[4] = {a0, a1, a2, a3};
            #pragma unroll
            for (int f = 0; f < 4; f++) {
                u64 aa = pk2(av[f], av[f]);
                const ulonglong2* wr = w0v + ((l * 4 + f) << 4);
                #pragma unroll
                for (int jj = 0; jj < 16; jj++) {
                    ulonglong2 wp = wr[jj];
                    ffma2(h2[2 * jj + 0], aa, wp.x);
                    ffma2(h2[2 * jj + 1], aa, wp.y);
                }
            }
        }

        // relu boundary: unpack, clamp, spill to smem
        #pragma unroll
        for (int j = 0; j < 32; j++) {
            float2 t = up2(h2[j]);
            sact[(2 * j + 0) * BLOCK2 + tid] = fmaxf(t.x, 0.f);
            sact[(2 * j + 1) * BLOCK2 + tid] = fmaxf(t.y, 0.f);
            h2[j] = 0ull;
        }

        // layer 2: FFMA2
        #pragma unroll 4
        for (int i = 0; i < 64; i++) {
            float v = sact[i * BLOCK2 + tid];
            u64 vv = pk2(v, v);
            const ulonglong2* wr = w1v + (i << 4);
            #pragma unroll
            for (int jj = 0; jj < 16; jj++) {
                ulonglong2 wp = wr[jj];
                ffma2(h2[2 * jj + 0], vv, wp.x);
                ffma2(h2[2 * jj + 1], vv, wp.y);
            }
        }

        // layer 3: directly from packed h1 registers (no second spill)
        float o[8];
        #pragma unroll
        for (int k = 0; k < 8; k++) o[k] = 0.f;
        #pragma unroll 8
        for (int j = 0; j < 32; j++) {
            float2 t = up2(h2[j]);
            float va = fmaxf(t.x, 0.f);
            float vb = fmaxf(t.y, 0.f);
            const float4* wr = (const float4*)(sw2 + ((2 * j) << 3));
            float4 wa = wr[0], wb4 = wr[1];   // row 2j
            float4 wc = wr[2], wd = wr[3];    // row 2j+1
            o[0] += va * wa.x + vb * wc.x;
            o[1] += va * wa.y + vb * wc.y;
            o[2] += va * wa.z + vb * wc.z;
            o[3] += va * wa.w + vb * wc.w;
            o[4] += va * wb4.x + vb * wd.x;
            o[5] += va * wb4.y + vb * wd.y;
            o[6] += va * wb4.z + vb * wd.z;
            o[7] += va * wb4.w + vb * wd.w;
        }

        if (active) {
            dxyz[3 * ipt + 0] = o[0];
            dxyz[3 * ipt + 1] = o[1];
            dxyz[3 * ipt + 2] = o[2];
            drot[4 * ipt + 0] = o[3];
            drot[4 * ipt + 1] = o[4];
            drot[4 * ipt + 2] = o[5];
            drot[4 * ipt + 3] = o[6];
        }
    }
}

// ---------------- launch ----------------
extern "C" void kernel_launch(void* const* d_in, const int* in_sizes, int n_in,
                              void* d_out, int out_size)
{
    const float* xyz   = (const float*)d_in[0];
    const float* bmin  = (const float*)d_in[1];
    const float* bmax  = (const float*)d_in[2];
    const float* table = (const float*)d_in[3];
    const float* w0    = (const float*)d_in[4];
    const float* w1    = (const float*)d_in[5];
    const float* w2    = (const float*)d_in[6];
    int N = in_sizes[0] / 3;
    float* out = (float*)d_out;

    void* ptr = nullptr;
    cudaGetSymbolAddress(&ptr, g_count);
    cudaMemsetAsync(ptr, 0, sizeof(int), 0);
    cudaGetSymbolAddress(&ptr, g_hist);
    cudaMemsetAsync(ptr, 0, NBINS * sizeof(int), 0);
    cudaGetSymbolAddress(&ptr, g_tile);
    cudaMemsetAsync(ptr, 0, sizeof(int), 0);

    int grid1 = CONV_BLOCKS + (N + 255) / 256;
    k_convert_mask<<<grid1, 256>>>(table, xyz, bmin, bmax, out, N);   // #1
    k_scanA<<<64, 128>>>();                                           // #2
    k_scatter<<<512, 256>>>();                                        // #3
    cudaFuncSetAttribute(k_encode_mlp,
                         cudaFuncAttributeMaxDynamicSharedMemorySize, SMEM_BYTES);
    k_encode_mlp<<<444, BLOCK2, SMEM_BYTES>>>(w0, w1, w2, out, N);    // #4
}